// round 1
// baseline (speedup 1.0000x reference)
#include <cuda_runtime.h>

// SlidingMean: out = (x - boxfilter_79x69(x)) / 5, SAME (zero) padding.
// Separable: vertical 79-tap sliding sum -> horizontal 69-tap window via
// per-row prefix sum -> fused normalize epilogue.

#define HH 512
#define WW 512
#define NB 32
#define KH 79
#define KW 69
#define RH 39   // (KH-1)/2
#define RW 34   // (KW-1)/2

// Scratch for column sums (device global: no allocation allowed in kernel_launch)
__device__ float g_colsum[(size_t)NB * HH * WW];

// ---------------------------------------------------------------------------
// Kernel 1: vertical sliding sum over 79 rows, zero padding outside [0,512).
// Grid: NB * 4 (h-chunks of 128) * 2 (w-chunks of 256). Block: 256 threads,
// one thread per column within the w-chunk. Warp reads are contiguous in W.
// ---------------------------------------------------------------------------
__global__ __launch_bounds__(256) void vert_sum_kernel(const float* __restrict__ x) {
    const int HC = 128;
    int bid = blockIdx.x;
    int wc = bid & 1;          // 0..1
    int hc = (bid >> 1) & 3;   // 0..3
    int n  = bid >> 3;         // 0..31
    int w  = wc * 256 + threadIdx.x;
    int h0 = hc * HC;

    const float* __restrict__ xp = x + (size_t)n * HH * WW + w;
    float* __restrict__ cp = g_colsum + (size_t)n * HH * WW + w;

    // Initialize window sum for output row h0: rows [h0-RH, h0+RH] clamped.
    float s = 0.0f;
    int lo = h0 - RH; if (lo < 0) lo = 0;
    int hi = h0 + RH; if (hi > HH - 1) hi = HH - 1;
    for (int r = lo; r <= hi; ++r) s += xp[(size_t)r * WW];

    #pragma unroll 4
    for (int h = h0; h < h0 + HC; ++h) {
        cp[(size_t)h * WW] = s;
        int add = h + RH + 1;
        int sub = h - RH;
        if (add < HH) s += xp[(size_t)add * WW];
        if (sub >= 0) s -= xp[(size_t)sub * WW];
    }
}

// ---------------------------------------------------------------------------
// Kernel 2: horizontal 69-tap window via per-row inclusive prefix sum
// (shfl warp scans + warp-aggregate), then fused epilogue:
//     out = (x - winsum/(KH*KW)) * (1/STD)
// Grid: NB*HH blocks (one row each). Block: 512 threads (one per w).
// ---------------------------------------------------------------------------
__global__ __launch_bounds__(512) void horiz_norm_kernel(const float* __restrict__ x,
                                                         float* __restrict__ out) {
    __shared__ float P[WW];      // inclusive prefix of colsum row
    __shared__ float wsums[16];  // per-warp totals

    int row = blockIdx.x;                 // 0 .. NB*HH-1
    size_t base = (size_t)row * WW;
    int t = threadIdx.x;
    unsigned lane = t & 31;
    unsigned wid  = t >> 5;

    float v = g_colsum[base + t];

    // warp inclusive scan
    float s = v;
    #pragma unroll
    for (int off = 1; off < 32; off <<= 1) {
        float u = __shfl_up_sync(0xffffffffu, s, off);
        if (lane >= off) s += u;
    }
    if (lane == 31) wsums[wid] = s;
    __syncthreads();

    // scan the 16 warp totals in warp 0
    if (wid == 0 && lane < 16) {
        float ws = wsums[lane];
        #pragma unroll
        for (int off = 1; off < 16; off <<= 1) {
            float u = __shfl_up_sync(0x0000ffffu, ws, off);
            if (lane >= off) ws += u;
        }
        wsums[lane] = ws;
    }
    __syncthreads();

    float offv = (wid > 0) ? wsums[wid - 1] : 0.0f;
    P[t] = s + offv;
    __syncthreads();

    // window sum over [t-RW, t+RW] with zero padding:
    // winsum = P[min(t+RW, W-1)] - (t-RW-1 >= 0 ? P[t-RW-1] : 0)
    int hiI = t + RW; if (hiI > WW - 1) hiI = WW - 1;
    int loI = t - RW - 1;
    float winsum = P[hiI] - (loI >= 0 ? P[loI] : 0.0f);

    const float inv_cnt = 1.0f / (float)(KH * KW);
    const float inv_std = 0.2f;  // 1/5
    out[base + t] = (x[base + t] - winsum * inv_cnt) * inv_std;
}

extern "C" void kernel_launch(void* const* d_in, const int* in_sizes, int n_in,
                              void* d_out, int out_size) {
    const float* x = (const float*)d_in[0];
    float* out = (float*)d_out;

    vert_sum_kernel<<<NB * 4 * 2, 256>>>(x);
    horiz_norm_kernel<<<NB * HH, 512>>>(x, out);
}

// round 2
// speedup vs baseline: 2.6969x; 2.6969x over previous
#include <cuda_runtime.h>

// SlidingMean fused: out = (x - boxfilter_79x69(x)) / 5, SAME (zero) padding.
// One kernel: vertical 79-tap sliding sum into smem (per 32-row stripe),
// then per-warp horizontal prefix-sum (carry scan) + windowed difference +
// normalize epilogue. No global scratch, no second pass over DRAM.

#define HH 512
#define WW 512
#define NB 32
#define KH 79
#define KW 69
#define RH 39   // (KH-1)/2
#define RW 34   // (KW-1)/2
#define TH 32   // output rows per block

__global__ __launch_bounds__(512) void sliding_mean_fused(const float* __restrict__ x,
                                                          float* __restrict__ out) {
    extern __shared__ float smemC[];   // [TH][WW] column sums -> row prefixes (in place)

    const int blk = blockIdx.x;
    const int hc = blk & 15;           // 16 h-chunks
    const int n  = blk >> 4;           // batch
    const int h0 = hc * TH;
    const int t  = threadIdx.x;        // 0..511 = column index in phase A

    const size_t gbase = (size_t)n * HH * WW;
    const float* __restrict__ xp = x + gbase + t;

    // ---------------- Phase A: vertical sliding sum (thread = one column) ----
    float s = 0.0f;
    {
        int lo = h0 - RH; if (lo < 0) lo = 0;
        int hi = h0 + RH; if (hi > HH - 1) hi = HH - 1;
        for (int r = lo; r <= hi; ++r) s += xp[(size_t)r * WW];
    }
    #pragma unroll 8
    for (int k = 0; k < TH; ++k) {
        smemC[k * WW + t] = s;
        int add = h0 + k + RH + 1;
        int sub = h0 + k - RH;
        float a = (add < HH) ? xp[(size_t)add * WW] : 0.0f;
        float b = (sub >= 0) ? xp[(size_t)sub * WW] : 0.0f;
        s += a - b;
    }
    __syncthreads();

    // ---------------- Phase B: per-warp horizontal prefix (2 rows/warp) ------
    const unsigned FULL = 0xffffffffu;
    const int lane = t & 31;
    const int wrp  = t >> 5;
    const int r0 = wrp * 2;
    const int r1 = r0 + 1;
    float* __restrict__ C0 = smemC + r0 * WW;
    float* __restrict__ C1 = smemC + r1 * WW;

    float c0 = 0.0f, c1 = 0.0f;
    #pragma unroll
    for (int i = 0; i < 16; ++i) {
        float v0 = C0[i * 32 + lane];
        float v1 = C1[i * 32 + lane];
        // dual interleaved warp inclusive scans
        #pragma unroll
        for (int off = 1; off < 32; off <<= 1) {
            float u0 = __shfl_up_sync(FULL, v0, off);
            float u1 = __shfl_up_sync(FULL, v1, off);
            if (lane >= off) { v0 += u0; v1 += u1; }
        }
        v0 += c0; v1 += c1;
        C0[i * 32 + lane] = v0;   // in-place: colsum -> inclusive prefix
        C1[i * 32 + lane] = v1;
        c0 = __shfl_sync(FULL, v0, 31);
        c1 = __shfl_sync(FULL, v1, 31);
    }
    __syncwarp();  // only this warp touches rows r0/r1

    // ---------------- Epilogue: window diff + normalize ----------------------
    const float inv_cnt = 1.0f / (float)(KH * KW);
    const float inv_std = 0.2f;  // 1/5
    #pragma unroll
    for (int i = 0; i < 16; ++i) {
        int w = i * 32 + lane;
        int hiI = w + RW; if (hiI > WW - 1) hiI = WW - 1;
        int loI = w - RW - 1;
        float lo0 = 0.0f, lo1 = 0.0f;
        if (loI >= 0) { lo0 = C0[loI]; lo1 = C1[loI]; }
        float ws0 = C0[hiI] - lo0;
        float ws1 = C1[hiI] - lo1;
        size_t o0 = gbase + (size_t)(h0 + r0) * WW + w;
        size_t o1 = gbase + (size_t)(h0 + r1) * WW + w;
        out[o0] = (x[o0] - ws0 * inv_cnt) * inv_std;
        out[o1] = (x[o1] - ws1 * inv_cnt) * inv_std;
    }
}

extern "C" void kernel_launch(void* const* d_in, const int* in_sizes, int n_in,
                              void* d_out, int out_size) {
    const float* x = (const float*)d_in[0];
    float* out = (float*)d_out;

    const int smem_bytes = TH * WW * (int)sizeof(float);   // 64 KB
    cudaFuncSetAttribute(sliding_mean_fused,
                         cudaFuncAttributeMaxDynamicSharedMemorySize, smem_bytes);

    sliding_mean_fused<<<NB * (HH / TH), 512, smem_bytes>>>(x, out);
}

// round 3
// speedup vs baseline: 3.8985x; 1.4455x over previous
#include <cuda_runtime.h>

// SlidingMean fused: out = (x - boxfilter_79x69(x)) / 5, SAME (zero) padding.
// One kernel, 16-row stripes: vertical 79-tap sliding sum -> swizzled smem ->
// per-warp register prefix scan (5 shfls) -> coalesced windowed epilogue.

#define HH 512
#define WW 512
#define NB 32
#define KH 79
#define KW 69
#define RH 39   // (KH-1)/2
#define RW 34   // (KW-1)/2
#define TH 16   // output rows per block (= 1 row per warp in phase B)

// XOR swizzle on 16B units within a 2KB row: conflict-free for
//  - scalar stores at consecutive elements (phase A)
//  - float4 loads at unit 4*lane (phase B)
//  - scalar loads at consecutive elements (epilogue)
__device__ __forceinline__ int swz(int e) {
    int u = e >> 2;
    int pu = u ^ ((u >> 3) & 7);
    return (pu << 2) | (e & 3);
}

__global__ __launch_bounds__(512, 4) void sliding_mean_fused(const float* __restrict__ x,
                                                             float* __restrict__ out) {
    __shared__ float smemC[TH * WW];   // column sums -> row prefixes (in place, swizzled)

    const int blk = blockIdx.x;
    const int hc = blk & 31;           // 32 h-chunks of 16 rows
    const int n  = blk >> 5;           // batch
    const int h0 = hc * TH;
    const int t  = threadIdx.x;        // 0..511 = column index in phase A

    const size_t gbase = (size_t)n * HH * WW;
    const float* __restrict__ xp = x + gbase + t;
    const int st = swz(t);             // swizzled store slot for this column

    // ---------------- Phase A: vertical sliding sum (thread = one column) ----
    if (h0 >= RH + 1 + 8 && h0 + TH - 1 + RH + 1 <= HH - 1) {
        // fully interior: no boundary predicates
        float s0 = 0.f, s1 = 0.f, s2 = 0.f, s3 = 0.f;
        const float* p = xp + (size_t)(h0 - RH) * WW;
        #pragma unroll
        for (int r = 0; r < 76; r += 4) {
            s0 += p[(size_t)(r + 0) * WW];
            s1 += p[(size_t)(r + 1) * WW];
            s2 += p[(size_t)(r + 2) * WW];
            s3 += p[(size_t)(r + 3) * WW];
        }
        float s = (s0 + s1) + (s2 + s3)
                + p[(size_t)76 * WW] + p[(size_t)77 * WW] + p[(size_t)78 * WW];
        #pragma unroll
        for (int k = 0; k < TH; ++k) {
            smemC[(k << 9) + st] = s;
            s += xp[(size_t)(h0 + k + RH + 1) * WW] - xp[(size_t)(h0 + k - RH) * WW];
        }
    } else {
        // boundary chunk: clamped init + guarded updates
        float s = 0.f;
        int lo = h0 - RH; if (lo < 0) lo = 0;
        int hi = h0 + RH; if (hi > HH - 1) hi = HH - 1;
        for (int r = lo; r <= hi; ++r) s += xp[(size_t)r * WW];
        #pragma unroll
        for (int k = 0; k < TH; ++k) {
            smemC[(k << 9) + st] = s;
            int add = h0 + k + RH + 1;
            int sub = h0 + k - RH;
            float a = (add < HH) ? xp[(size_t)add * WW] : 0.f;
            float b = (sub >= 0) ? xp[(size_t)sub * WW] : 0.f;
            s += a - b;
        }
    }
    __syncthreads();

    // ---------------- Phase B: per-warp row prefix scan in registers ---------
    const unsigned FULL = 0xffffffffu;
    const int lane = t & 31;
    const int wrp  = t >> 5;            // warp = row index (16 warps, 16 rows)
    float* __restrict__ row = smemC + (wrp << 9);

    // load 16 contiguous elements (elements 16*lane .. 16*lane+15) via 4 swizzled float4
    float p[16];
    #pragma unroll
    for (int c = 0; c < 4; ++c) {
        int u = (lane << 2) + c;
        int pu = u ^ ((u >> 3) & 7);
        float4 v = *reinterpret_cast<const float4*>(row + (pu << 2));
        p[c * 4 + 0] = v.x; p[c * 4 + 1] = v.y; p[c * 4 + 2] = v.z; p[c * 4 + 3] = v.w;
    }
    // local inclusive prefix
    #pragma unroll
    for (int j = 1; j < 16; ++j) p[j] += p[j - 1];
    // warp scan of totals -> exclusive offset
    float tot = p[15];
    float inc = tot;
    #pragma unroll
    for (int off = 1; off < 32; off <<= 1) {
        float u = __shfl_up_sync(FULL, inc, off);
        if (lane >= off) inc += u;
    }
    float excl = inc - tot;
    #pragma unroll
    for (int j = 0; j < 16; ++j) p[j] += excl;
    // write prefix back (same swizzled addresses)
    #pragma unroll
    for (int c = 0; c < 4; ++c) {
        int u = (lane << 2) + c;
        int pu = u ^ ((u >> 3) & 7);
        float4 v = make_float4(p[c * 4 + 0], p[c * 4 + 1], p[c * 4 + 2], p[c * 4 + 3]);
        *reinterpret_cast<float4*>(row + (pu << 2)) = v;
    }
    __syncwarp();  // only this warp touches this row

    // ---------------- Epilogue: window diff + normalize (fully coalesced) ----
    const float inv_cnt = 1.0f / (float)(KH * KW);
    const float inv_std = 0.2f;  // 1/5
    const size_t rbase = gbase + (size_t)(h0 + wrp) * WW;
    #pragma unroll
    for (int i = 0; i < 16; ++i) {
        int w = lane + (i << 5);
        int hiI = w + RW; if (hiI > WW - 1) hiI = WW - 1;
        int loI = w - RW - 1;
        float hi = row[swz(hiI)];
        float lo = (loI >= 0) ? row[swz(loI)] : 0.0f;
        float winsum = hi - lo;
        size_t o = rbase + w;
        out[o] = (x[o] - winsum * inv_cnt) * inv_std;
    }
}

extern "C" void kernel_launch(void* const* d_in, const int* in_sizes, int n_in,
                              void* d_out, int out_size) {
    const float* x = (const float*)d_in[0];
    float* out = (float*)d_out;
    sliding_mean_fused<<<NB * (HH / TH), 512>>>(x, out);
}